// round 14
// baseline (speedup 1.0000x reference)
#include <cuda_runtime.h>
#include <math.h>

#define NT 128
#define GZ (-9.80665f)

struct SM {
    float A[441], Pn[441], T9[189], L[108];
    float G[36], GA[42], HP[42], S3[3];
    float Rotn[9], vi3[3], Om3[3], vns[3], pns[3], r2s[2], dxs[21];
    float mir[33];     // Rot 0-8, V 9-11, Pp 12-14, Bom 15-17, Bac 18-20, Rci 21-29, Tci 30-32
    float in[2][9];    // t, u[6], mcov[2]
};

__device__ __forceinline__ float skf(const float* w, int r, int c) {
    if (r == 0) return (c == 0) ? 0.f : ((c == 1) ? -w[2] : w[1]);
    if (r == 1) return (c == 0) ? w[2] : ((c == 1) ? 0.f : -w[0]);
    return (c == 0) ? -w[1] : ((c == 1) ? w[0] : 0.f);
}
__device__ __forceinline__ float skewrowdot(const float* w, const float* R, int rr, int j) {
    if (rr == 0) return -w[2]*R[3+j] + w[1]*R[6+j];
    if (rr == 1) return  w[2]*R[0+j] - w[0]*R[6+j];
    return -w[1]*R[0+j] + w[0]*R[3+j];
}
__device__ __forceinline__ float SG(int rr, int j) {
    if (rr == 0 && j == 1) return -GZ;
    if (rr == 1 && j == 0) return  GZ;
    return 0.f;
}
__device__ __forceinline__ float sgR(const float* R, int rr, int j) {
    if (rr == 0) return -GZ * R[3+j];
    if (rr == 1) return  GZ * R[0+j];
    return 0.f;
}
__device__ __forceinline__ void so3c(float a2, float& c, float& sa, float& oc) {
    c  = 1.f + a2*(-0.5f      + a2*((1.f/24.f)  + a2*(-1.f/720.f)));
    sa = 1.f + a2*((-1.f/6.f) + a2*((1.f/120.f) + a2*(-1.f/5040.f)));
    oc = 0.5f + a2*((-1.f/24.f) + a2*(1.f/720.f));
}
__device__ __forceinline__ float j1c(float a2) {
    return (1.f/6.f) + a2*((-1.f/120.f) + a2*(1.f/5040.f));
}
__device__ __forceinline__ void mm3(const float* A, const float* B, float* C) {
#pragma unroll
    for (int p = 0; p < 3; ++p)
#pragma unroll
        for (int q = 0; q < 3; ++q)
            C[p*3+q] = A[p*3+0]*B[0*3+q] + A[p*3+1]*B[1*3+q] + A[p*3+2]*B[2*3+q];
}
__device__ __forceinline__ void normrot(float* X) {
    for (int it = 0; it < 8; ++it) {
        float Y[9], Z[9];
#pragma unroll
        for (int p = 0; p < 3; ++p)
#pragma unroll
            for (int q = 0; q < 3; ++q)
                Y[p*3+q] = X[p*3+0]*X[q*3+0] + X[p*3+1]*X[q*3+1] + X[p*3+2]*X[q*3+2];
        mm3(Y, X, Z);
#pragma unroll
        for (int m = 0; m < 9; ++m) X[m] = 1.5f*X[m] - 0.5f*Z[m];
    }
}

__global__ void __launch_bounds__(NT, 1)
iekf_kernel(const float* __restrict__ t, const float* __restrict__ u,
            const float* __restrict__ mc, const float* __restrict__ vmes,
            const float* __restrict__ ang0, float* __restrict__ out, int N)
{
    __shared__ SM s;
    const int tid = threadIdx.x;
    const bool isMat = (tid < 96);
    const int ln = tid - 96;

    // ---------- matrix decodes: 5 slots/thread over 96 threads ----------
    bool eV[5]; int eII[5], eJJ[5], eJJT[5], eIIB[5], eJJ12[5];
    int eAm[5], eAr[5], eBrx[5]; float eAsc[5], eAqv[5]; bool eT9f[5];
#pragma unroll
    for (int sl = 0; sl < 5; ++sl) {
        int e = tid + sl*96;
        eV[sl] = isMat && (e < 441);
        int ii = 0, jj = 0;
        if (eV[sl]) { ii = e/21; jj = e - ii*21; }
        eII[sl]=ii; eJJ[sl]=jj; eJJT[sl]=jj*21+ii; eIIB[sl]=ii*21; eJJ12[sl]=jj*12;
        eT9f[sl] = (ii < 9);
        int am = 2, ar = 0, brx = 0; float asc = 0.f, aqv = 0.f;
        if (ii<3 && jj<3)                      { am=0; ar=ii*3;     brx=jj*3;     asc=0.001f; }
        else if (ii>=3&&ii<6&&jj>=3&&jj<6)     { am=0; ar=(ii-3)*3; brx=(jj-3)*3; asc=0.01f;  }
        else if (ii==jj) { am=1; aqv=(ii>=9&&ii<12)?6e-9f:(ii>=12&&ii<15)?2e-4f:(ii>=15)?1e-9f:0.f; }
        eAm[sl]=am; eAr[sl]=ar; eBrx[sl]=brx; eAsc[sl]=asc; eAqv[sl]=aqv;
    }
    // T9 slots
    const int t9aR12 = (tid/21)*12, t9aC = tid - (tid/21)*21;
    const int t9k2 = tid + 96; const bool t9bV = isMat && (t9k2 < 189);
    int t9bR12 = 0, t9bC = 0;
    if (t9bV) { int r = t9k2/21; t9bR12 = r*12; t9bC = t9k2 - r*21; }
    // L decodes
    int Lbrr = 0, Lrr = 0, Lbc = 0, Lj = 0;
    if (isMat) {
        int r = tid/12, cc = tid - r*12;
        Lbrr = r/3; Lrr = r - Lbrr*3; Lbc = cc/3; Lj = cc - Lbc*3;
    }
    const bool l2V = isMat && (tid < 12);
    const int L2bc = tid/3, L2j = tid - L2bc*3;
    // out pointers (tid<33)
    float* outP = out; int outStride = 0;
    if (tid < 9)       { outP = out + tid;              outStride = 9; }
    else if (tid < 12) { outP = out + 9*N  + (tid-9);   outStride = 3; }
    else if (tid < 15) { outP = out + 12*N + (tid-12);  outStride = 3; }
    else if (tid < 18) { outP = out + 15*N + (tid-15);  outStride = 3; }
    else if (tid < 21) { outP = out + 18*N + (tid-18);  outStride = 3; }
    else if (tid < 30) { outP = out + 21*N + (tid-21);  outStride = 9; }
    else if (tid < 33) { outP = out + 30*N + (tid-30);  outStride = 3; }
    // prefetch pointers (tid 64..72)
    const float* pfP = t; int pfStride = 0;
    const bool pfV = (tid >= 64 && tid < 73);
    if (pfV) {
        int q = tid - 64;
        if (q == 0)      { pfP = t  + 2;           pfStride = 1; }
        else if (q < 7)  { pfP = u  + 12 + (q-1);  pfStride = 6; }
        else             { pfP = mc + 4  + (q-7);  pfStride = 2; }
    }

    // ---------- prologue ----------
    float tprev = t[0];
#pragma unroll
    for (int sl = 0; sl < 5; ++sl) if (eV[sl]) {
        int e = tid + sl*96;
        int ii = eII[sl], jj = eJJ[sl];
        float pv = 0.f;
        if (ii == jj) {
            if (ii < 2) pv = 0.001f;
            else if (ii >= 3 && ii < 5) pv = 0.1f;
            else if (ii >= 9 && ii < 12) pv = 0.006f;
            else if (ii >= 12 && ii < 15) pv = 0.004f;
            else if (ii >= 15 && ii < 18) pv = 1e-6f;
            else if (ii >= 18) pv = 0.005f;
        }
        s.Pn[e] = pv;
    }
    if (tid < 42) s.HP[tid] = 0.f;
    if (tid == 42) { s.S3[0] = 1.f; s.S3[1] = 0.f; s.S3[2] = 1.f; }
    if (tid < 9) {
        float v;
        if (tid == 0) v = t[1];
        else if (tid < 7) v = u[6 + (tid-1)];
        else v = mc[2 + (tid-7)];
        s.in[1][tid] = v;
    }
    if (tid == 96) {
        float a0 = ang0[0], a1 = ang0[1], a2 = ang0[2];
        float cr = cosf(a0), sr = sinf(a0), cp = cosf(a1), sp = sinf(a1);
        float cy = cosf(a2), sy = sinf(a2);
        float Rx[9] = {1,0,0, 0,cr,-sr, 0,sr,cr};
        float Ry[9] = {cp,0,sp, 0,1,0, -sp,0,cp};
        float Rz[9] = {cy,-sy,0, sy,cy,0, 0,0,1};
        float T[9], R0[9];
        mm3(Rz, Ry, T); mm3(T, Rx, R0);
#pragma unroll
        for (int m = 0; m < 9; ++m) { s.mir[m] = R0[m]; s.mir[21+m] = (m==0||m==4||m==8) ? 1.f : 0.f; }
#pragma unroll
        for (int q = 0; q < 3; ++q) {
            s.mir[9+q] = vmes[q]; s.mir[12+q] = 0.f; s.mir[15+q] = 0.f;
            s.mir[18+q] = 0.f; s.mir[30+q] = 0.f;
        }
    }
    __syncthreads();

    // ---------- main loop ----------
    for (int i = 1; i < N; ++i) {
        const int cur = i & 1;
        const float tcv = s.in[cur][0];
        const float dt = tcv - tprev; tprev = tcv;
        const float dt2 = dt*dt;

        // ======== PHASE 1: mat {A=Joseph+gq, L, out, pf-LDG} ; w3 {meas chain 3-way} ========
        float pf = 0.f;
        if (isMat) {
            const float dt3 = dt2*dt;
            const float S00 = s.S3[0], S01 = s.S3[1], S11 = s.S3[2];
            const float idet = 1.f / (S00*S11 - S01*S01);
            const float Si00 = S11*idet, Si01 = -S01*idet, Si11 = S00*idet;
#pragma unroll
            for (int sl = 0; sl < 5; ++sl) if (eV[sl]) {
                int e = tid + sl*96;
                float hp0i = s.HP[eII[sl]], hp1i = s.HP[21+eII[sl]];
                float hp0j = s.HP[eJJ[sl]], hp1j = s.HP[21+eJJ[sl]];
                float Ki0 = Si00*hp0i + Si01*hp1i, Ki1 = Si01*hp0i + Si11*hp1i;
                float Kj0 = Si00*hp0j + Si01*hp1j, Kj1 = Si01*hp0j + Si11*hp1j;
                float KSi0 = Ki0*S00 + Ki1*S01, KSi1 = Ki0*S01 + Ki1*S11;
                float pj = 0.5f*(s.Pn[e] + s.Pn[eJJT[sl]])
                         - (Ki0*hp0j + Ki1*hp1j) - (Kj0*hp0i + Kj1*hp1i)
                         + (KSi0*Kj0 + KSi1*Kj1);
                float gq = 0.f;
                if (eAm[sl] == 0) {
                    float d = s.mir[eAr[sl]]*s.mir[eBrx[sl]] + s.mir[eAr[sl]+1]*s.mir[eBrx[sl]+1]
                            + s.mir[eAr[sl]+2]*s.mir[eBrx[sl]+2];
                    gq = eAsc[sl] * dt2 * d;
                } else if (eAm[sl] == 1) gq = eAqv[sl] * dt2;
                s.A[e] = pj + gq;
            }
            {
                const float* Rm = s.mir; const float* Vm = s.mir + 9; const float* Pm = s.mir + 12;
                float v = 0.f;
                if (Lbrr == 0) {
                    if (Lbc == 2) v = -dt * Rm[Lrr*3+Lj];
                } else if (Lbrr == 1) {
                    if (Lbc == 0)      v = dt * SG(Lrr, Lj);
                    else if (Lbc == 2) v = -dt*skewrowdot(Vm, Rm, Lrr, Lj) - 0.5f*dt2*sgR(Rm, Lrr, Lj);
                    else if (Lbc == 3) v = -dt * Rm[Lrr*3+Lj];
                } else {
                    if (Lbc == 0)      v = 0.5f*dt2*SG(Lrr, Lj);
                    else if (Lbc == 1) v = (Lrr == Lj) ? dt : 0.f;
                    else if (Lbc == 2) v = -dt*skewrowdot(Pm, Rm, Lrr, Lj)
                                           - 0.5f*dt2*skewrowdot(Vm, Rm, Lrr, Lj)
                                           - (dt3*(1.f/6.f))*sgR(Rm, Lrr, Lj);
                    else               v = -0.5f*dt2*Rm[Lrr*3+Lj];
                }
                s.L[tid] = v;
                if (l2V) {
                    float v2 = 0.f;
                    if (L2bc == 0)      v2 = 0.5f*dt2*SG(2, L2j);
                    else if (L2bc == 1) v2 = (2 == L2j) ? dt : 0.f;
                    else if (L2bc == 2) v2 = -dt*skewrowdot(Pm, Rm, 2, L2j)
                                             - 0.5f*dt2*skewrowdot(Vm, Rm, 2, L2j)
                                             - (dt3*(1.f/6.f))*sgR(Rm, 2, L2j);
                    else                v2 = -0.5f*dt2*Rm[6+L2j];
                    s.L[96+tid] = v2;
                }
            }
            if (tid < 33) { *outP = s.mir[tid]; outP += outStride; }
            if (pfV && (i + 1 < N)) { pf = *pfP; pfP += pfStride; }
        } else {
            // ---- stage 1a (lanes 0-2): rn row p, vn[p], pn3[p], Om3[p] ----
            if (ln < 3) {
                const int p = ln;
                const float gy0 = s.in[cur][1], gy1 = s.in[cur][2], gy2 = s.in[cur][3];
                const float ac0 = s.in[cur][4], ac1 = s.in[cur][5], ac2 = s.in[cur][6];
                float om0 = gy0 - s.mir[15], om1 = gy1 - s.mir[16], om2 = gy2 - s.mir[17];
                s.Om3[p] = (p==0)?om0:(p==1)?om1:om2;
                float phi[3] = {om0*dt, om1*dt, om2*dt};
                float a2 = phi[0]*phi[0] + phi[1]*phi[1] + phi[2]*phi[2];
                float c, sa, oc; so3c(a2, c, sa, oc);
                float E[9];
#pragma unroll
                for (int k = 0; k < 3; ++k)
#pragma unroll
                    for (int q = 0; q < 3; ++q)
                        E[k*3+q] = ((k==q)?c:0.f) + oc*phi[k]*phi[q] + sa*skf(phi, k, q);
                float r0 = s.mir[p*3+0], r1 = s.mir[p*3+1], r2v = s.mir[p*3+2];
#pragma unroll
                for (int q = 0; q < 3; ++q)
                    s.Rotn[p*3+q] = r0*E[0*3+q] + r1*E[1*3+q] + r2v*E[2*3+q];
                float d0 = ac0 - s.mir[18], d1 = ac1 - s.mir[19], d2 = ac2 - s.mir[20];
                float accp = r0*d0 + r1*d1 + r2v*d2 + ((p==2)?GZ:0.f);
                s.vns[p] = s.mir[9+p] + accp*dt;
                s.pns[p] = s.mir[12+p] + s.mir[9+p]*dt + 0.5f*accp*dt2;
            }
            __syncwarp();
            // ---- stage 1b (lanes 0-2): vi3 ----
            if (ln < 3) {
                s.vi3[ln] = s.Rotn[ln]*s.vns[0] + s.Rotn[3+ln]*s.vns[1] + s.Rotn[6+ln]*s.vns[2];
            }
            __syncwarp();
            // ---- stage 2 (lanes 0,1): h/g row a, r2[a] ----
            if (ln < 2) {
                const int a = ln;
                const float* Rm  = s.mir;
                const float* Vm  = s.mir + 9;
                const float* Rc  = s.mir + 21;
                const float* Tc  = s.mir + 30;
                const float* rns = s.Rotn;
                const float* vis = s.vi3;
                const float* oms = s.Om3;
                float h[12];
#pragma unroll
                for (int j = 0; j < 3; ++j) {
                    h[j]     = rns[j*3+0]*Rc[a+1] + rns[j*3+1]*Rc[3+a+1] + rns[j*3+2]*Rc[6+a+1];
                    h[3+j]   = skf(Tc, a+1, j);
                    h[6+j]   = Rc[a+1]*skf(vis,0,j) + Rc[3+a+1]*skf(vis,1,j) + Rc[6+a+1]*skf(vis,2,j);
                    h[9+j]   = -skf(oms, a+1, j);
                }
                float Lv[9];
#pragma unroll
                for (int rr = 0; rr < 3; ++rr)
#pragma unroll
                    for (int j = 0; j < 3; ++j)
                        Lv[rr*3+j] = -dt*skewrowdot(Vm, Rm, rr, j) - 0.5f*dt2*sgR(Rm, rr, j);
                float g[18];
                g[0] =  h[1]*(dt*GZ);
                g[1] = -h[0]*(dt*GZ);
                g[2] = 0.f;
#pragma unroll
                for (int j = 0; j < 3; ++j) g[3+j] = h[j];
#pragma unroll
                for (int j = 0; j < 3; ++j)
                    g[6+j] = h[3+j] + h[0]*Lv[j] + h[1]*Lv[3+j] + h[2]*Lv[6+j];
#pragma unroll
                for (int j = 0; j < 3; ++j)
                    g[9+j] = -dt*(h[0]*Rm[j] + h[1]*Rm[3+j] + h[2]*Rm[6+j]);
#pragma unroll
                for (int m = 12; m < 18; ++m) g[m] = h[m-6];
#pragma unroll
                for (int m = 0; m < 18; ++m) s.G[a*18+m] = g[m];
                float cxa = (a==0) ? (Tc[2]*oms[0] - Tc[0]*oms[2])
                                   : (Tc[0]*oms[1] - Tc[1]*oms[0]);
                s.r2s[a] = -(Rc[a+1]*vis[0] + Rc[3+a+1]*vis[1] + Rc[6+a+1]*vis[2] + cxa);
            }
        }
        __syncthreads();

        // ======== PHASE 2 (overlapped): mat {T9 -> bar96 -> Pn, pf-STS} ; w3 {GA -> HP,S -> dx -> state 4-way} ========
        if (isMat) {
            float a = s.A[tid];
#pragma unroll
            for (int m = 0; m < 12; ++m) {
                int col = (m < 6) ? m : m + 3;
                a += s.L[t9aR12+m] * s.A[col*21 + t9aC];
            }
            s.T9[tid] = a;
            if (t9bV) {
                float b = s.A[t9k2];
#pragma unroll
                for (int m = 0; m < 12; ++m) {
                    int col = (m < 6) ? m : m + 3;
                    b += s.L[t9bR12+m] * s.A[col*21 + t9bC];
                }
                s.T9[t9k2] = b;
            }
            asm volatile("bar.sync 1, 96;" ::: "memory");
#pragma unroll
            for (int sl = 0; sl < 5; ++sl) if (eV[sl]) {
                int e = tid + sl*96;
                float b = eT9f[sl] ? s.T9[e] : s.A[e];
                if (eJJ[sl] < 9) {
#pragma unroll
                    for (int m = 0; m < 12; ++m) {
                        int col = (m < 6) ? m : m + 3;
                        float brc = eT9f[sl] ? s.T9[eIIB[sl]+col] : s.A[eIIB[sl]+col];
                        b += brc * s.L[eJJ12[sl]+m];
                    }
                }
                s.Pn[e] = b;
            }
            if (pfV && (i + 1 < N)) s.in[cur^1][tid-64] = pf;
        } else {
            // ---- GA ----
            if (ln < 21) {
                float a0 = 0.f, a1 = 0.f;
#pragma unroll
                for (int m = 0; m < 18; ++m) {
                    int col = (m < 6) ? m : m + 3;
                    float av = s.A[col*21 + ln];
                    a0 += s.G[m]      * av;
                    a1 += s.G[18+m]   * av;
                }
                s.GA[ln] = a0; s.GA[21+ln] = a1;
            }
            __syncwarp();
            // ---- HP, S ----
            if (ln < 21) {
                float hp0 = s.GA[ln], hp1 = s.GA[21+ln];
                if (ln < 9) {
#pragma unroll
                    for (int m = 0; m < 12; ++m) {
                        int col = (m < 6) ? m : m + 3;
                        float lv = s.L[ln*12+m];
                        hp0 += s.GA[col]    * lv;
                        hp1 += s.GA[21+col] * lv;
                    }
                }
                s.HP[ln] = hp0; s.HP[21+ln] = hp1;
            } else if (ln < 24) {
                int m2 = ln - 21;
                int a = (m2 == 2) ? 1 : 0;
                int bb = (m2 == 0) ? 0 : 1;
                float acc = 0.f;
#pragma unroll
                for (int mm = 0; mm < 18; ++mm) {
                    int col = (mm < 6) ? mm : mm + 3;
                    acc += s.GA[a*21+col] * s.G[bb*18+mm];
                }
                if (a == bb) acc += s.in[cur][7+a];
                s.S3[m2] = acc;
            }
            __syncwarp();
            // ---- dx ----
            if (ln < 21) {
                const float S00 = s.S3[0], S01 = s.S3[1], S11 = s.S3[2];
                const float idet = 1.f / (S00*S11 - S01*S01);
                const float r0 = s.r2s[0], r1 = s.r2s[1];
                const float w0 = idet*( S11*r0 - S01*r1);
                const float w1 = idet*(-S01*r0 + S00*r1);
                s.dxs[ln] = s.HP[ln]*w0 + s.HP[21+ln]*w1;
            }
            __syncwarp();
            // ---- state update: lanes 0-2 row q of SE23 part; lane 3 Rci ----
            if (ln < 3) {
                const int q = ln;
                float dx[9];
#pragma unroll
                for (int m = 0; m < 9; ++m) dx[m] = s.dxs[m];
                float a2 = dx[0]*dx[0] + dx[1]*dx[1] + dx[2]*dx[2];
                float c, sa, oc; so3c(a2, c, sa, oc);
                float j1 = j1c(a2);
                float dR0 = ((q==0)?c:0.f) + oc*dx[q]*dx[0] + sa*skf(dx, q, 0);
                float dR1 = ((q==1)?c:0.f) + oc*dx[q]*dx[1] + sa*skf(dx, q, 1);
                float dR2 = ((q==2)?c:0.f) + oc*dx[q]*dx[2] + sa*skf(dx, q, 2);
                float J0  = ((q==0)?sa:0.f) + j1*dx[q]*dx[0] + oc*skf(dx, q, 0);
                float J1  = ((q==1)?sa:0.f) + j1*dx[q]*dx[1] + oc*skf(dx, q, 1);
                float J2  = ((q==2)?sa:0.f) + j1*dx[q]*dx[2] + oc*skf(dx, q, 2);
                float x0 = J0*dx[3] + J1*dx[4] + J2*dx[5];
                float x1 = J0*dx[6] + J1*dx[7] + J2*dx[8];
                float ru0 = dR0*s.Rotn[0] + dR1*s.Rotn[3] + dR2*s.Rotn[6];
                float ru1 = dR0*s.Rotn[1] + dR1*s.Rotn[4] + dR2*s.Rotn[7];
                float ru2 = dR0*s.Rotn[2] + dR1*s.Rotn[5] + dR2*s.Rotn[8];
                float vu = dR0*s.vns[0] + dR1*s.vns[1] + dR2*s.vns[2] + x0;
                float pu = dR0*s.pns[0] + dR1*s.pns[1] + dR2*s.pns[2] + x1;
                float bo = s.mir[15+q] + s.dxs[9+q];
                float ba = s.mir[18+q] + s.dxs[12+q];
                float tc2 = s.mir[30+q] + s.dxs[18+q];
                s.mir[q*3+0] = ru0; s.mir[q*3+1] = ru1; s.mir[q*3+2] = ru2;
                s.mir[9+q] = vu; s.mir[12+q] = pu;
                s.mir[15+q] = bo; s.mir[18+q] = ba; s.mir[30+q] = tc2;
            } else if (ln == 3) {
                float y0 = s.dxs[15], y1 = s.dxs[16], y2 = s.dxs[17];
                float b2 = y0*y0 + y1*y1 + y2*y2;
                float cc2, sa2, oc2; so3c(b2, cc2, sa2, oc2);
                float yv[3] = {y0, y1, y2};
                float E2[9];
#pragma unroll
                for (int p = 0; p < 3; ++p)
#pragma unroll
                    for (int q = 0; q < 3; ++q)
                        E2[p*3+q] = ((p==q)?cc2:0.f) + oc2*yv[p]*yv[q] + sa2*skf(yv, p, q);
                float Rc2[9];
#pragma unroll
                for (int p = 0; p < 3; ++p)
#pragma unroll
                    for (int q = 0; q < 3; ++q)
                        Rc2[p*3+q] = E2[p*3+0]*s.mir[21+q] + E2[p*3+1]*s.mir[24+q] + E2[p*3+2]*s.mir[27+q];
#pragma unroll
                for (int m = 0; m < 9; ++m) s.mir[21+m] = Rc2[m];
            }
            __syncwarp();
            // ---- amortized renormalization ----
            if (i % 100 == 0) {
                if (ln == 0) {
                    float X[9];
#pragma unroll
                    for (int m = 0; m < 9; ++m) X[m] = s.mir[m];
                    normrot(X);
#pragma unroll
                    for (int m = 0; m < 9; ++m) s.mir[m] = X[m];
                }
                if ((i % 1000 == 0) && ln == 1) {
                    float X[9];
#pragma unroll
                    for (int m = 0; m < 9; ++m) X[m] = s.mir[21+m];
                    normrot(X);
#pragma unroll
                    for (int m = 0; m < 9; ++m) s.mir[21+m] = X[m];
                }
            }
        }
        __syncthreads();
    }

    // ---------- epilogue: final state row ----------
    if (tid < 33) *outP = s.mir[tid];
}

extern "C" void kernel_launch(void* const* d_in, const int* in_sizes, int n_in,
                              void* d_out, int out_size) {
    const float* t    = (const float*)d_in[0];
    const float* u    = (const float*)d_in[1];
    const float* mcov = (const float*)d_in[2];
    const float* vmes = (const float*)d_in[3];
    const float* ang0 = (const float*)d_in[5];
    float* out = (float*)d_out;
    int N = in_sizes[0];
    iekf_kernel<<<1, NT>>>(t, u, mcov, vmes, ang0, out, N);
}

// round 17
// speedup vs baseline: 1.0830x; 1.0830x over previous
#include <cuda_runtime.h>
#include <math.h>

#define NT 128
#define GZ (-9.80665f)

struct SM {
    float A[441], Pn[441], T9[189], L[108];
    float G[36], GA[42], HP[42], S3[3];
    float Rotn[9], vi3[3], Om3[3], vns[3], pns[3], r2s[2], dxs[21];
    float mir[33];     // Rot 0-8, V 9-11, Pp 12-14, Bom 15-17, Bac 18-20, Rci 21-29, Tci 30-32
    float in[2][9];    // t, u[6], mcov[2]
};

__device__ __forceinline__ float skf(const float* w, int r, int c) {
    if (r == 0) return (c == 0) ? 0.f : ((c == 1) ? -w[2] : w[1]);
    if (r == 1) return (c == 0) ? w[2] : ((c == 1) ? 0.f : -w[0]);
    return (c == 0) ? -w[1] : ((c == 1) ? w[0] : 0.f);
}
__device__ __forceinline__ float skewrowdot(const float* w, const float* R, int rr, int j) {
    if (rr == 0) return -w[2]*R[3+j] + w[1]*R[6+j];
    if (rr == 1) return  w[2]*R[0+j] - w[0]*R[6+j];
    return -w[1]*R[0+j] + w[0]*R[3+j];
}
__device__ __forceinline__ float SG(int rr, int j) {
    if (rr == 0 && j == 1) return -GZ;
    if (rr == 1 && j == 0) return  GZ;
    return 0.f;
}
__device__ __forceinline__ float sgR(const float* R, int rr, int j) {
    if (rr == 0) return -GZ * R[3+j];
    if (rr == 1) return  GZ * R[0+j];
    return 0.f;
}
__device__ __forceinline__ void so3c(float a2, float& c, float& sa, float& oc) {
    c  = 1.f + a2*(-0.5f      + a2*((1.f/24.f)  + a2*(-1.f/720.f)));
    sa = 1.f + a2*((-1.f/6.f) + a2*((1.f/120.f) + a2*(-1.f/5040.f)));
    oc = 0.5f + a2*((-1.f/24.f) + a2*(1.f/720.f));
}
__device__ __forceinline__ float j1c(float a2) {
    return (1.f/6.f) + a2*((-1.f/120.f) + a2*(1.f/5040.f));
}
__device__ __forceinline__ void mm3(const float* A, const float* B, float* C) {
#pragma unroll
    for (int p = 0; p < 3; ++p)
#pragma unroll
        for (int q = 0; q < 3; ++q)
            C[p*3+q] = A[p*3+0]*B[0*3+q] + A[p*3+1]*B[1*3+q] + A[p*3+2]*B[2*3+q];
}
__device__ __forceinline__ void normrot(float* X) {
    for (int it = 0; it < 8; ++it) {
        float Y[9], Z[9];
#pragma unroll
        for (int p = 0; p < 3; ++p)
#pragma unroll
            for (int q = 0; q < 3; ++q)
                Y[p*3+q] = X[p*3+0]*X[q*3+0] + X[p*3+1]*X[q*3+1] + X[p*3+2]*X[q*3+2];
        mm3(Y, X, Z);
#pragma unroll
        for (int m = 0; m < 9; ++m) X[m] = 1.5f*X[m] - 0.5f*Z[m];
    }
}

__global__ void __launch_bounds__(NT, 1)
iekf_kernel(const float* __restrict__ t, const float* __restrict__ u,
            const float* __restrict__ mc, const float* __restrict__ vmes,
            const float* __restrict__ ang0, float* __restrict__ out, int N)
{
    __shared__ SM s;
    const int tid = threadIdx.x;
    const bool isMat = (tid < 96);
    const int ln = tid - 96;

    // ---------- matrix decodes: 5 slots/thread over 96 threads ----------
    bool eV[5]; int eII[5], eJJ[5], eJJT[5], eIIB[5], eJJ12[5];
    int eAm[5], eAr[5], eBrx[5]; float eAsc[5], eAqv[5]; bool eT9f[5];
#pragma unroll
    for (int sl = 0; sl < 5; ++sl) {
        int e = tid + sl*96;
        eV[sl] = isMat && (e < 441);
        int ii = 0, jj = 0;
        if (eV[sl]) { ii = e/21; jj = e - ii*21; }
        eII[sl]=ii; eJJ[sl]=jj; eJJT[sl]=jj*21+ii; eIIB[sl]=ii*21; eJJ12[sl]=jj*12;
        eT9f[sl] = (ii < 9);
        int am = 2, ar = 0, brx = 0; float asc = 0.f, aqv = 0.f;
        if (ii<3 && jj<3)                      { am=0; ar=ii*3;     brx=jj*3;     asc=0.001f; }
        else if (ii>=3&&ii<6&&jj>=3&&jj<6)     { am=0; ar=(ii-3)*3; brx=(jj-3)*3; asc=0.01f;  }
        else if (ii==jj) { am=1; aqv=(ii>=9&&ii<12)?6e-9f:(ii>=12&&ii<15)?2e-4f:(ii>=15)?1e-9f:0.f; }
        eAm[sl]=am; eAr[sl]=ar; eBrx[sl]=brx; eAsc[sl]=asc; eAqv[sl]=aqv;
    }
    // T9 slots
    const int t9aR12 = (tid/21)*12, t9aC = tid - (tid/21)*21;
    const int t9k2 = tid + 96; const bool t9bV = isMat && (t9k2 < 189);
    int t9bR12 = 0, t9bC = 0;
    if (t9bV) { int r = t9k2/21; t9bR12 = r*12; t9bC = t9k2 - r*21; }
    // L decodes
    int Lbrr = 0, Lrr = 0, Lbc = 0, Lj = 0;
    if (isMat) {
        int r = tid/12, cc = tid - r*12;
        Lbrr = r/3; Lrr = r - Lbrr*3; Lbc = cc/3; Lj = cc - Lbc*3;
    }
    const bool l2V = isMat && (tid < 12);
    const int L2bc = tid/3, L2j = tid - L2bc*3;
    // out pointers (tid<33)
    float* outP = out; int outStride = 0;
    if (tid < 9)       { outP = out + tid;              outStride = 9; }
    else if (tid < 12) { outP = out + 9*N  + (tid-9);   outStride = 3; }
    else if (tid < 15) { outP = out + 12*N + (tid-12);  outStride = 3; }
    else if (tid < 18) { outP = out + 15*N + (tid-15);  outStride = 3; }
    else if (tid < 21) { outP = out + 18*N + (tid-18);  outStride = 3; }
    else if (tid < 30) { outP = out + 21*N + (tid-21);  outStride = 9; }
    else if (tid < 33) { outP = out + 30*N + (tid-30);  outStride = 3; }
    // prefetch pointers (tid 64..72)
    const float* pfP = t; int pfStride = 0;
    const bool pfV = (tid >= 64 && tid < 73);
    if (pfV) {
        int q = tid - 64;
        if (q == 0)      { pfP = t  + 2;           pfStride = 1; }
        else if (q < 7)  { pfP = u  + 12 + (q-1);  pfStride = 6; }
        else             { pfP = mc + 4  + (q-7);  pfStride = 2; }
    }

    // ---------- prologue ----------
    float tprev = t[0];
#pragma unroll
    for (int sl = 0; sl < 5; ++sl) if (eV[sl]) {
        int e = tid + sl*96;
        int ii = eII[sl], jj = eJJ[sl];
        float pv = 0.f;
        if (ii == jj) {
            if (ii < 2) pv = 0.001f;
            else if (ii >= 3 && ii < 5) pv = 0.1f;
            else if (ii >= 9 && ii < 12) pv = 0.006f;
            else if (ii >= 12 && ii < 15) pv = 0.004f;
            else if (ii >= 15 && ii < 18) pv = 1e-6f;
            else if (ii >= 18) pv = 0.005f;
        }
        s.Pn[e] = pv;
    }
    if (tid < 42) s.HP[tid] = 0.f;
    if (tid == 42) { s.S3[0] = 1.f; s.S3[1] = 0.f; s.S3[2] = 1.f; }
    if (tid < 9) {
        float v;
        if (tid == 0) v = t[1];
        else if (tid < 7) v = u[6 + (tid-1)];
        else v = mc[2 + (tid-7)];
        s.in[1][tid] = v;
    }
    if (tid == 96) {
        float a0 = ang0[0], a1 = ang0[1], a2 = ang0[2];
        float cr = cosf(a0), sr = sinf(a0), cp = cosf(a1), sp = sinf(a1);
        float cy = cosf(a2), sy = sinf(a2);
        float Rx[9] = {1,0,0, 0,cr,-sr, 0,sr,cr};
        float Ry[9] = {cp,0,sp, 0,1,0, -sp,0,cp};
        float Rz[9] = {cy,-sy,0, sy,cy,0, 0,0,1};
        float T[9], R0[9];
        mm3(Rz, Ry, T); mm3(T, Rx, R0);
#pragma unroll
        for (int m = 0; m < 9; ++m) { s.mir[m] = R0[m]; s.mir[21+m] = (m==0||m==4||m==8) ? 1.f : 0.f; }
#pragma unroll
        for (int q = 0; q < 3; ++q) {
            s.mir[9+q] = vmes[q]; s.mir[12+q] = 0.f; s.mir[15+q] = 0.f;
            s.mir[18+q] = 0.f; s.mir[30+q] = 0.f;
        }
    }
    __syncthreads();

    // ---------- main loop ----------
    for (int i = 1; i < N; ++i) {
        const int cur = i & 1;
        const float tcv = s.in[cur][0];
        const float dt = tcv - tprev; tprev = tcv;
        const float dt2 = dt*dt;

        // ======== PHASE 1: mat {A=Joseph+gq, L, out, pf-LDG} ; w3 {meas chain} ========
        float pf = 0.f;
        if (isMat) {
            const float dt3 = dt2*dt;
            const float S00 = s.S3[0], S01 = s.S3[1], S11 = s.S3[2];
            const float idet = 1.f / (S00*S11 - S01*S01);
            const float Si00 = S11*idet, Si01 = -S01*idet, Si11 = S00*idet;
#pragma unroll
            for (int sl = 0; sl < 5; ++sl) if (eV[sl]) {
                int e = tid + sl*96;
                float hp0i = s.HP[eII[sl]], hp1i = s.HP[21+eII[sl]];
                float hp0j = s.HP[eJJ[sl]], hp1j = s.HP[21+eJJ[sl]];
                float Ki0 = Si00*hp0i + Si01*hp1i, Ki1 = Si01*hp0i + Si11*hp1i;
                float Kj0 = Si00*hp0j + Si01*hp1j, Kj1 = Si01*hp0j + Si11*hp1j;
                float KSi0 = Ki0*S00 + Ki1*S01, KSi1 = Ki0*S01 + Ki1*S11;
                float pj = 0.5f*(s.Pn[e] + s.Pn[eJJT[sl]])
                         - (Ki0*hp0j + Ki1*hp1j) - (Kj0*hp0i + Kj1*hp1i)
                         + (KSi0*Kj0 + KSi1*Kj1);
                float gq = 0.f;
                if (eAm[sl] == 0) {
                    float d = s.mir[eAr[sl]]*s.mir[eBrx[sl]] + s.mir[eAr[sl]+1]*s.mir[eBrx[sl]+1]
                            + s.mir[eAr[sl]+2]*s.mir[eBrx[sl]+2];
                    gq = eAsc[sl] * dt2 * d;
                } else if (eAm[sl] == 1) gq = eAqv[sl] * dt2;
                s.A[e] = pj + gq;
            }
            {
                const float* Rm = s.mir; const float* Vm = s.mir + 9; const float* Pm = s.mir + 12;
                float v = 0.f;
                if (Lbrr == 0) {
                    if (Lbc == 2) v = -dt * Rm[Lrr*3+Lj];
                } else if (Lbrr == 1) {
                    if (Lbc == 0)      v = dt * SG(Lrr, Lj);
                    else if (Lbc == 2) v = -dt*skewrowdot(Vm, Rm, Lrr, Lj) - 0.5f*dt2*sgR(Rm, Lrr, Lj);
                    else if (Lbc == 3) v = -dt * Rm[Lrr*3+Lj];
                } else {
                    if (Lbc == 0)      v = 0.5f*dt2*SG(Lrr, Lj);
                    else if (Lbc == 1) v = (Lrr == Lj) ? dt : 0.f;
                    else if (Lbc == 2) v = -dt*skewrowdot(Pm, Rm, Lrr, Lj)
                                           - 0.5f*dt2*skewrowdot(Vm, Rm, Lrr, Lj)
                                           - (dt3*(1.f/6.f))*sgR(Rm, Lrr, Lj);
                    else               v = -0.5f*dt2*Rm[Lrr*3+Lj];
                }
                s.L[tid] = v;
                if (l2V) {
                    float v2 = 0.f;
                    if (L2bc == 0)      v2 = 0.5f*dt2*SG(2, L2j);
                    else if (L2bc == 1) v2 = (2 == L2j) ? dt : 0.f;
                    else if (L2bc == 2) v2 = -dt*skewrowdot(Pm, Rm, 2, L2j)
                                             - 0.5f*dt2*skewrowdot(Vm, Rm, 2, L2j)
                                             - (dt3*(1.f/6.f))*sgR(Rm, 2, L2j);
                    else                v2 = -0.5f*dt2*Rm[6+L2j];
                    s.L[96+tid] = v2;
                }
            }
            if (tid < 33) { *outP = s.mir[tid]; outP += outStride; }
            if (pfV && (i + 1 < N)) { pf = *pfP; pfP += pfStride; }
        } else {
            // ---- stage 1 (lane 0): omg, rn, vn, pn3, vi3 ----
            if (ln == 0) {
                const float gy0 = s.in[cur][1], gy1 = s.in[cur][2], gy2 = s.in[cur][3];
                const float ac0 = s.in[cur][4], ac1 = s.in[cur][5], ac2 = s.in[cur][6];
                float om0 = gy0 - s.mir[15], om1 = gy1 - s.mir[16], om2 = gy2 - s.mir[17];
                s.Om3[0] = om0; s.Om3[1] = om1; s.Om3[2] = om2;
                float phi[3] = {om0*dt, om1*dt, om2*dt};
                float a2 = phi[0]*phi[0] + phi[1]*phi[1] + phi[2]*phi[2];
                float c, sa, oc; so3c(a2, c, sa, oc);
                float E[9];
#pragma unroll
                for (int p = 0; p < 3; ++p)
#pragma unroll
                    for (int q = 0; q < 3; ++q)
                        E[p*3+q] = ((p==q)?c:0.f) + oc*phi[p]*phi[q] + sa*skf(phi, p, q);
                float rn[9];
#pragma unroll
                for (int p = 0; p < 3; ++p)
#pragma unroll
                    for (int q = 0; q < 3; ++q) {
                        rn[p*3+q] = s.mir[p*3+0]*E[0*3+q] + s.mir[p*3+1]*E[1*3+q] + s.mir[p*3+2]*E[2*3+q];
                        s.Rotn[p*3+q] = rn[p*3+q];
                    }
                float d0 = ac0 - s.mir[18], d1 = ac1 - s.mir[19], d2 = ac2 - s.mir[20];
                float vn[3];
#pragma unroll
                for (int q = 0; q < 3; ++q) {
                    float accq = s.mir[q*3+0]*d0 + s.mir[q*3+1]*d1 + s.mir[q*3+2]*d2 + ((q==2)?GZ:0.f);
                    vn[q] = s.mir[9+q] + accq*dt;
                    s.vns[q] = vn[q];
                    s.pns[q] = s.mir[12+q] + s.mir[9+q]*dt + 0.5f*accq*dt2;
                }
#pragma unroll
                for (int q = 0; q < 3; ++q)
                    s.vi3[q] = rn[0*3+q]*vn[0] + rn[3+q]*vn[1] + rn[6+q]*vn[2];
            }
            __syncwarp();
            // ---- stage 2 (lanes 0,1): h/g row a, r2[a] ----
            if (ln < 2) {
                const int a = ln;
                const float* Rm  = s.mir;
                const float* Vm  = s.mir + 9;
                const float* Rc  = s.mir + 21;
                const float* Tc  = s.mir + 30;
                const float* rns = s.Rotn;
                const float* vis = s.vi3;
                const float* oms = s.Om3;
                float h[12];
#pragma unroll
                for (int j = 0; j < 3; ++j) {
                    h[j]     = rns[j*3+0]*Rc[a+1] + rns[j*3+1]*Rc[3+a+1] + rns[j*3+2]*Rc[6+a+1];
                    h[3+j]   = skf(Tc, a+1, j);
                    h[6+j]   = Rc[a+1]*skf(vis,0,j) + Rc[3+a+1]*skf(vis,1,j) + Rc[6+a+1]*skf(vis,2,j);
                    h[9+j]   = -skf(oms, a+1, j);
                }
                float Lv[9];
#pragma unroll
                for (int rr = 0; rr < 3; ++rr)
#pragma unroll
                    for (int j = 0; j < 3; ++j)
                        Lv[rr*3+j] = -dt*skewrowdot(Vm, Rm, rr, j) - 0.5f*dt2*sgR(Rm, rr, j);
                float g[18];
                g[0] =  h[1]*(dt*GZ);
                g[1] = -h[0]*(dt*GZ);
                g[2] = 0.f;
#pragma unroll
                for (int j = 0; j < 3; ++j) g[3+j] = h[j];
#pragma unroll
                for (int j = 0; j < 3; ++j)
                    g[6+j] = h[3+j] + h[0]*Lv[j] + h[1]*Lv[3+j] + h[2]*Lv[6+j];
#pragma unroll
                for (int j = 0; j < 3; ++j)
                    g[9+j] = -dt*(h[0]*Rm[j] + h[1]*Rm[3+j] + h[2]*Rm[6+j]);
#pragma unroll
                for (int m = 12; m < 18; ++m) g[m] = h[m-6];
#pragma unroll
                for (int m = 0; m < 18; ++m) s.G[a*18+m] = g[m];
                float cxa = (a==0) ? (Tc[2]*oms[0] - Tc[0]*oms[2])
                                   : (Tc[0]*oms[1] - Tc[1]*oms[0]);
                s.r2s[a] = -(Rc[a+1]*vis[0] + Rc[3+a+1]*vis[1] + Rc[6+a+1]*vis[2] + cxa);
            }
        }
        __syncthreads();

        // ======== PHASE 2 (overlapped): mat {T9 -> bar96 -> Pn, pf-STS} ; w3 {GA -> HP,S -> dx -> state} ========
        if (isMat) {
            float a = s.A[tid];
#pragma unroll
            for (int m = 0; m < 12; ++m) {
                int col = (m < 6) ? m : m + 3;
                a += s.L[t9aR12+m] * s.A[col*21 + t9aC];
            }
            s.T9[tid] = a;
            if (t9bV) {
                float b = s.A[t9k2];
#pragma unroll
                for (int m = 0; m < 12; ++m) {
                    int col = (m < 6) ? m : m + 3;
                    b += s.L[t9bR12+m] * s.A[col*21 + t9bC];
                }
                s.T9[t9k2] = b;
            }
            asm volatile("bar.sync 1, 96;" ::: "memory");
#pragma unroll
            for (int sl = 0; sl < 5; ++sl) if (eV[sl]) {
                int e = tid + sl*96;
                float b = eT9f[sl] ? s.T9[e] : s.A[e];
                if (eJJ[sl] < 9) {
#pragma unroll
                    for (int m = 0; m < 12; ++m) {
                        int col = (m < 6) ? m : m + 3;
                        float brc = eT9f[sl] ? s.T9[eIIB[sl]+col] : s.A[eIIB[sl]+col];
                        b += brc * s.L[eJJ12[sl]+m];
                    }
                }
                s.Pn[e] = b;
            }
            if (pfV && (i + 1 < N)) s.in[cur^1][tid-64] = pf;
        } else {
            // ---- GA ----
            if (ln < 21) {
                float a0 = 0.f, a1 = 0.f;
#pragma unroll
                for (int m = 0; m < 18; ++m) {
                    int col = (m < 6) ? m : m + 3;
                    float av = s.A[col*21 + ln];
                    a0 += s.G[m]      * av;
                    a1 += s.G[18+m]   * av;
                }
                s.GA[ln] = a0; s.GA[21+ln] = a1;
            }
            __syncwarp();
            // ---- HP, S ----
            if (ln < 21) {
                float hp0 = s.GA[ln], hp1 = s.GA[21+ln];
                if (ln < 9) {
#pragma unroll
                    for (int m = 0; m < 12; ++m) {
                        int col = (m < 6) ? m : m + 3;
                        float lv = s.L[ln*12+m];
                        hp0 += s.GA[col]    * lv;
                        hp1 += s.GA[21+col] * lv;
                    }
                }
                s.HP[ln] = hp0; s.HP[21+ln] = hp1;
            } else if (ln < 24) {
                int m2 = ln - 21;
                int a = (m2 == 2) ? 1 : 0;
                int bb = (m2 == 0) ? 0 : 1;
                float acc = 0.f;
#pragma unroll
                for (int mm = 0; mm < 18; ++mm) {
                    int col = (mm < 6) ? mm : mm + 3;
                    acc += s.GA[a*21+col] * s.G[bb*18+mm];
                }
                if (a == bb) acc += s.in[cur][7+a];
                s.S3[m2] = acc;
            }
            __syncwarp();
            // ---- dx ----
            if (ln < 21) {
                const float S00 = s.S3[0], S01 = s.S3[1], S11 = s.S3[2];
                const float idet = 1.f / (S00*S11 - S01*S01);
                const float r0 = s.r2s[0], r1 = s.r2s[1];
                const float w0 = idet*( S11*r0 - S01*r1);
                const float w1 = idet*(-S01*r0 + S00*r1);
                s.dxs[ln] = s.HP[ln]*w0 + s.HP[21+ln]*w1;
            }
            __syncwarp();
            // ---- state update: UNIFORM over lanes 0-5 (q = ln%3; se = ln<3) ----
            if (ln < 6) {
                const bool se = (ln < 3);
                const int q = se ? ln : ln - 3;
                const float p0 = se ? s.dxs[0] : s.dxs[15];
                const float p1 = se ? s.dxs[1] : s.dxs[16];
                const float p2 = se ? s.dxs[2] : s.dxs[17];
                float ph[3] = {p0, p1, p2};
                float a2 = p0*p0 + p1*p1 + p2*p2;
                float c, sa, oc; so3c(a2, c, sa, oc);
                float d0 = ((q==0)?c:0.f) + oc*ph[q]*p0 + sa*skf(ph, q, 0);
                float d1 = ((q==1)?c:0.f) + oc*ph[q]*p1 + sa*skf(ph, q, 1);
                float d2 = ((q==2)?c:0.f) + oc*ph[q]*p2 + sa*skf(ph, q, 2);
                if (se) {
                    float j1 = j1c(a2);
                    float J0 = ((q==0)?sa:0.f) + j1*ph[q]*p0 + oc*skf(ph, q, 0);
                    float J1 = ((q==1)?sa:0.f) + j1*ph[q]*p1 + oc*skf(ph, q, 1);
                    float J2 = ((q==2)?sa:0.f) + j1*ph[q]*p2 + oc*skf(ph, q, 2);
                    float x0 = J0*s.dxs[3] + J1*s.dxs[4] + J2*s.dxs[5];
                    float x1 = J0*s.dxs[6] + J1*s.dxs[7] + J2*s.dxs[8];
                    float ru0 = d0*s.Rotn[0] + d1*s.Rotn[3] + d2*s.Rotn[6];
                    float ru1 = d0*s.Rotn[1] + d1*s.Rotn[4] + d2*s.Rotn[7];
                    float ru2 = d0*s.Rotn[2] + d1*s.Rotn[5] + d2*s.Rotn[8];
                    float vu = d0*s.vns[0] + d1*s.vns[1] + d2*s.vns[2] + x0;
                    float pu = d0*s.pns[0] + d1*s.pns[1] + d2*s.pns[2] + x1;
                    float bo  = s.mir[15+q] + s.dxs[9+q];
                    float ba  = s.mir[18+q] + s.dxs[12+q];
                    float tc2 = s.mir[30+q] + s.dxs[18+q];
                    s.mir[q*3+0] = ru0; s.mir[q*3+1] = ru1; s.mir[q*3+2] = ru2;
                    s.mir[9+q] = vu; s.mir[12+q] = pu;
                    s.mir[15+q] = bo; s.mir[18+q] = ba; s.mir[30+q] = tc2;
                } else {
                    float rc0 = s.mir[21], rc1 = s.mir[22], rc2 = s.mir[23];
                    float rc3 = s.mir[24], rc4 = s.mir[25], rc5 = s.mir[26];
                    float rc6 = s.mir[27], rc7 = s.mir[28], rc8 = s.mir[29];
                    float o0 = d0*rc0 + d1*rc3 + d2*rc6;
                    float o1 = d0*rc1 + d1*rc4 + d2*rc7;
                    float o2 = d0*rc2 + d1*rc5 + d2*rc8;
                    s.mir[21+q*3+0] = o0; s.mir[21+q*3+1] = o1; s.mir[21+q*3+2] = o2;
                }
            }
            // ---- amortized renormalization ----
            if (i % 100 == 0) {
                __syncwarp();
                if (ln == 0) {
                    float X[9];
#pragma unroll
                    for (int m = 0; m < 9; ++m) X[m] = s.mir[m];
                    normrot(X);
#pragma unroll
                    for (int m = 0; m < 9; ++m) s.mir[m] = X[m];
                }
                if ((i % 1000 == 0) && ln == 1) {
                    float X[9];
#pragma unroll
                    for (int m = 0; m < 9; ++m) X[m] = s.mir[21+m];
                    normrot(X);
#pragma unroll
                    for (int m = 0; m < 9; ++m) s.mir[21+m] = X[m];
                }
            }
        }
        __syncthreads();
    }

    // ---------- epilogue: final state row ----------
    if (tid < 33) *outP = s.mir[tid];
}

extern "C" void kernel_launch(void* const* d_in, const int* in_sizes, int n_in,
                              void* d_out, int out_size) {
    const float* t    = (const float*)d_in[0];
    const float* u    = (const float*)d_in[1];
    const float* mcov = (const float*)d_in[2];
    const float* vmes = (const float*)d_in[3];
    const float* ang0 = (const float*)d_in[5];
    float* out = (float*)d_out;
    int N = in_sizes[0];
    iekf_kernel<<<1, NT>>>(t, u, mcov, vmes, ang0, out, N);
}